// round 5
// baseline (speedup 1.0000x reference)
#include <cuda_runtime.h>
#include <cuda_fp16.h>
#include <math.h>

#define N 8192
#define D 256
#define LAMF 10.0f
#define INV_LAM 0.1f
#define NEG_LAM_LOGN (-90.109133472792885f)
#define INV_N 1.220703125e-4f     // 1/8192

#define FROWS 16
#define FBLOCKS (N / FROWS)       // 512 row-chunks / partials
#define P2 16                     // second-stage partial count

// ---- scratch (static device globals; no allocation allowed) ----
__device__ float  g_C[(size_t)N * N];   // fp32 cost matrix (final pass only)
__device__ __half g_E[(size_t)N * N];   // exp(-C/lam) fp16 (iteration passes)
__device__ float  g_f[N];
__device__ float  g_g[N];
__device__ float  g_s[N];               // row sums s_i
__device__ float  g_S[N];               // col sums S'_j
__device__ float  g_Eg[N];              // exp(g/lam) = (1/N)/S'
__device__ float  g_x2[N];
__device__ float  g_y2[N];
__device__ float  g_part[(size_t)FBLOCKS * N];   // 16 MB col partials
__device__ float  g_p2[(size_t)P2 * N];
__device__ float  g_cost[N];

// ============================================================
// 1) row norms of X and Y
// ============================================================
__global__ __launch_bounds__(256) void norms_kernel(const float* __restrict__ X,
                                                    const float* __restrict__ Y) {
    int r = blockIdx.x;
    const float* src = (r < N) ? (X + (size_t)r * D) : (Y + (size_t)(r - N) * D);
    float v = src[threadIdx.x];
    v *= v;
    __shared__ float sh[256];
    sh[threadIdx.x] = v;
    __syncthreads();
    for (int off = 128; off > 0; off >>= 1) {
        if (threadIdx.x < off) sh[threadIdx.x] += sh[threadIdx.x + off];
        __syncthreads();
    }
    if (threadIdx.x == 0) {
        if (r < N) g_x2[r] = sh[0];
        else       g_y2[r - N] = sh[0];
    }
}

// ============================================================
// 2) GEMM: C = sqrt(max(x2+y2-2XY^T,0)+1e-6), also E = exp(-C/lam) fp16
// ============================================================
#define GBM 128
#define GBN 128
#define GBK 16

__global__ __launch_bounds__(256) void cost_gemm(const float* __restrict__ X,
                                                 const float* __restrict__ Y) {
    __shared__ float Xs[GBK][GBM + 4];
    __shared__ float Ys[GBK][GBN + 4];

    const int tid = threadIdx.x;
    const int bm = blockIdx.y * GBM;
    const int bn = blockIdx.x * GBN;
    const int tx = tid & 15;
    const int ty = tid >> 4;
    const int lr = tid >> 2;
    const int lk = (tid & 3) * 4;

    float acc[8][8];
#pragma unroll
    for (int i = 0; i < 8; i++)
#pragma unroll
        for (int j = 0; j < 8; j++) acc[i][j] = 0.0f;

    for (int k0 = 0; k0 < D; k0 += GBK) {
#pragma unroll
        for (int h = 0; h < 2; h++) {
            int row = lr + h * 64;
            float4 v = *(const float4*)&X[(size_t)(bm + row) * D + k0 + lk];
            Xs[lk + 0][row] = v.x; Xs[lk + 1][row] = v.y;
            Xs[lk + 2][row] = v.z; Xs[lk + 3][row] = v.w;
            float4 w = *(const float4*)&Y[(size_t)(bn + row) * D + k0 + lk];
            Ys[lk + 0][row] = w.x; Ys[lk + 1][row] = w.y;
            Ys[lk + 2][row] = w.z; Ys[lk + 3][row] = w.w;
        }
        __syncthreads();

#pragma unroll
        for (int k = 0; k < GBK; k++) {
            float a[8], b[8];
            *(float4*)&a[0] = *(const float4*)&Xs[k][ty * 8];
            *(float4*)&a[4] = *(const float4*)&Xs[k][ty * 8 + 4];
            *(float4*)&b[0] = *(const float4*)&Ys[k][tx * 8];
            *(float4*)&b[4] = *(const float4*)&Ys[k][tx * 8 + 4];
#pragma unroll
            for (int i = 0; i < 8; i++)
#pragma unroll
                for (int j = 0; j < 8; j++) acc[i][j] = fmaf(a[i], b[j], acc[i][j]);
        }
        __syncthreads();
    }

    float x2[8], y2[8];
#pragma unroll
    for (int i = 0; i < 8; i++) x2[i] = g_x2[bm + ty * 8 + i];
#pragma unroll
    for (int j = 0; j < 8; j++) y2[j] = g_y2[bn + tx * 8 + j];

#pragma unroll
    for (int i = 0; i < 8; i++) {
        size_t row = (size_t)(bm + ty * 8 + i);
        float c[8];
#pragma unroll
        for (int j = 0; j < 8; j++) {
            float sq = x2[i] + y2[j] - 2.0f * acc[i][j];
            c[j] = sqrtf(fmaxf(sq, 0.0f) + 1e-6f);
        }
        float* crow = g_C + row * N + bn + tx * 8;
        *(float4*)&crow[0] = make_float4(c[0], c[1], c[2], c[3]);
        *(float4*)&crow[4] = make_float4(c[4], c[5], c[6], c[7]);

        __half2 h0 = __floats2half2_rn(__expf(-c[0] * INV_LAM), __expf(-c[1] * INV_LAM));
        __half2 h1 = __floats2half2_rn(__expf(-c[2] * INV_LAM), __expf(-c[3] * INV_LAM));
        __half2 h2 = __floats2half2_rn(__expf(-c[4] * INV_LAM), __expf(-c[5] * INV_LAM));
        __half2 h3 = __floats2half2_rn(__expf(-c[6] * INV_LAM), __expf(-c[7] * INV_LAM));
        uint4 pk;
        pk.x = *(unsigned*)&h0; pk.y = *(unsigned*)&h1;
        pk.z = *(unsigned*)&h2; pk.w = *(unsigned*)&h3;
        *(uint4*)(g_E + row * N + bn + tx * 8) = pk;
    }
}

// ============================================================
// 3) init Eg = 1
// ============================================================
__global__ void init_g() {
    int j = blockIdx.x * 256 + threadIdx.x;
    g_Eg[j] = 1.0f;
}

// ============================================================
// 4) FUSED pass, high-occupancy version:
//    512 threads, 16 cols/thread, 16 rows/block,
//    ONE barrier per row (double-buffered warp partials,
//    redundant per-thread final sum), next-row preload.
// ============================================================
__global__ __launch_bounds__(512, 2) void fused_pass() {
    __shared__ float sEg[N];            // 32 KB
    __shared__ float swarp[2][16];
    const int tid = threadIdx.x;
    const int lane = tid & 31;
    const int wid = tid >> 5;

    for (int k = tid; k < N; k += 512) sEg[k] = g_Eg[k];
    __syncthreads();

    // thread's 16 columns: k*4096 + tid*8 + c, k in {0,1}
    float eg[2][8];
#pragma unroll
    for (int k = 0; k < 2; k++)
#pragma unroll
        for (int c = 0; c < 8; c++) eg[k][c] = sEg[k * 4096 + tid * 8 + c];

    const int i0 = blockIdx.x * FROWS;

    float acc[2][8];
#pragma unroll
    for (int k = 0; k < 2; k++)
#pragma unroll
        for (int c = 0; c < 8; c++) acc[k][c] = 0.0f;

    uint4 v[2];
    {
        const __half* __restrict__ row = g_E + (size_t)i0 * N;
        v[0] = *(const uint4*)(row + tid * 8);
        v[1] = *(const uint4*)(row + 4096 + tid * 8);
    }

#pragma unroll 1
    for (int r = 0; r < FROWS; r++) {
        // ---- dot with Eg ----
        float a0 = 0.0f, a1 = 0.0f;
#pragma unroll
        for (int k = 0; k < 2; k++) {
            const __half2* hp = (const __half2*)&v[k];
            float2 f0 = __half22float2(hp[0]);
            float2 f1 = __half22float2(hp[1]);
            float2 f2 = __half22float2(hp[2]);
            float2 f3 = __half22float2(hp[3]);
            a0 = fmaf(f0.x, eg[k][0], a0);
            a1 = fmaf(f0.y, eg[k][1], a1);
            a0 = fmaf(f1.x, eg[k][2], a0);
            a1 = fmaf(f1.y, eg[k][3], a1);
            a0 = fmaf(f2.x, eg[k][4], a0);
            a1 = fmaf(f2.y, eg[k][5], a1);
            a0 = fmaf(f3.x, eg[k][6], a0);
            a1 = fmaf(f3.y, eg[k][7], a1);
        }
        float p = a0 + a1;
#pragma unroll
        for (int o = 16; o > 0; o >>= 1)
            p += __shfl_down_sync(0xffffffffu, p, o);
        if (lane == 0) swarp[r & 1][wid] = p;

        // ---- preload next row before the barrier ----
        uint4 vn[2];
        {
            int rn = (r + 1 < FROWS) ? (r + 1) : r;
            const __half* __restrict__ rowp = g_E + (size_t)(i0 + rn) * N;
            vn[0] = *(const uint4*)(rowp + tid * 8);
            vn[1] = *(const uint4*)(rowp + 4096 + tid * 8);
        }
        __syncthreads();

        // ---- every thread sums the 16 warp partials (redundant, no 2nd barrier) ----
        float s = 0.0f;
#pragma unroll
        for (int w = 0; w < 16; w++) s += swarp[r & 1][w];
        if (tid == 0) g_s[i0 + r] = s;
        const float ef = INV_N / s;

        // ---- accumulate column partials with the SAME registers ----
#pragma unroll
        for (int k = 0; k < 2; k++) {
            const __half2* hp = (const __half2*)&v[k];
            float2 f0 = __half22float2(hp[0]);
            float2 f1 = __half22float2(hp[1]);
            float2 f2 = __half22float2(hp[2]);
            float2 f3 = __half22float2(hp[3]);
            acc[k][0] = fmaf(f0.x, ef, acc[k][0]);
            acc[k][1] = fmaf(f0.y, ef, acc[k][1]);
            acc[k][2] = fmaf(f1.x, ef, acc[k][2]);
            acc[k][3] = fmaf(f1.y, ef, acc[k][3]);
            acc[k][4] = fmaf(f2.x, ef, acc[k][4]);
            acc[k][5] = fmaf(f2.y, ef, acc[k][5]);
            acc[k][6] = fmaf(f3.x, ef, acc[k][6]);
            acc[k][7] = fmaf(f3.y, ef, acc[k][7]);
        }
        v[0] = vn[0];
        v[1] = vn[1];
    }

    float* part = g_part + (size_t)blockIdx.x * N;
#pragma unroll
    for (int k = 0; k < 2; k++) {
        *(float4*)&part[k * 4096 + tid * 8]     = make_float4(acc[k][0], acc[k][1], acc[k][2], acc[k][3]);
        *(float4*)&part[k * 4096 + tid * 8 + 4] = make_float4(acc[k][4], acc[k][5], acc[k][6], acc[k][7]);
    }
}

// ============================================================
// 5) combine stage 1: sum 32 of 512 partials -> g_p2[16][N]
// ============================================================
__global__ __launch_bounds__(256) void combine1() {
    const int j = blockIdx.x * 256 + threadIdx.x;
    const int c0 = blockIdx.y * (FBLOCKS / P2);
    float s = 0.0f;
#pragma unroll 8
    for (int c = 0; c < FBLOCKS / P2; c++)
        s += g_part[(size_t)(c0 + c) * N + j];
    g_p2[(size_t)blockIdx.y * N + j] = s;
}

// ============================================================
// 6) combine stage 2: S'_j, Eg = (1/N)/S'
// ============================================================
__global__ __launch_bounds__(256) void combine2() {
    const int j = blockIdx.x * 256 + threadIdx.x;
    float s = 0.0f;
#pragma unroll
    for (int c = 0; c < P2; c++) s += g_p2[(size_t)c * N + j];
    g_S[j] = s;
    g_Eg[j] = INV_N / s;
}

// ============================================================
// 7) finalize f, g (logs only here)
// ============================================================
__global__ __launch_bounds__(256) void final_fg() {
    const int i = blockIdx.x * 256 + threadIdx.x;
    g_f[i] = NEG_LAM_LOGN - LAMF * logf(g_s[i]);
    g_g[i] = NEG_LAM_LOGN - LAMF * logf(g_S[i]);
}

// ============================================================
// 8) final: pi = exp((f_i + g_j - C)/lam) from fp32 C; row cost partials
//    NOTE: out+1 is only 4-byte aligned -> SCALAR stores for pi.
// ============================================================
__global__ __launch_bounds__(256) void pi_cost(float* __restrict__ out) {
    const int i = blockIdx.x;
    const int tid = threadIdx.x;
    const float fi = g_f[i];
    const float* __restrict__ Crow = g_C + (size_t)i * N;
    float* __restrict__ orow = out + 1 + (size_t)i * N;

    float acc = 0.0f;
#pragma unroll
    for (int k = 0; k < 8; k++) {
        int j = (k * 256 + tid) * 4;
        float4 C4 = *(const float4*)&Crow[j];
        float4 G4 = *(const float4*)&g_g[j];
        float px = __expf((fi + G4.x - C4.x) * INV_LAM);
        float py = __expf((fi + G4.y - C4.y) * INV_LAM);
        float pz = __expf((fi + G4.z - C4.z) * INV_LAM);
        float pw = __expf((fi + G4.w - C4.w) * INV_LAM);
        orow[j + 0] = px;
        orow[j + 1] = py;
        orow[j + 2] = pz;
        orow[j + 3] = pw;
        acc = fmaf(px, C4.x, acc);
        acc = fmaf(py, C4.y, acc);
        acc = fmaf(pz, C4.z, acc);
        acc = fmaf(pw, C4.w, acc);
    }
    __shared__ float sh[256];
    sh[tid] = acc;
    __syncthreads();
    for (int off = 128; off > 0; off >>= 1) {
        if (tid < off) sh[tid] += sh[tid + off];
        __syncthreads();
    }
    if (tid == 0) g_cost[i] = sh[0];
}

// ============================================================
// 9) deterministic final cost reduction
// ============================================================
__global__ __launch_bounds__(1024) void cost_reduce(float* __restrict__ out) {
    __shared__ float sh[1024];
    float a = 0.0f;
    for (int k = threadIdx.x; k < N; k += 1024) a += g_cost[k];
    sh[threadIdx.x] = a;
    __syncthreads();
    for (int off = 512; off > 0; off >>= 1) {
        if (threadIdx.x < off) sh[threadIdx.x] += sh[threadIdx.x + off];
        __syncthreads();
    }
    if (threadIdx.x == 0) out[0] = sh[0];
}

// ============================================================
extern "C" void kernel_launch(void* const* d_in, const int* in_sizes, int n_in,
                              void* d_out, int out_size) {
    const float* X = (const float*)d_in[0];
    const float* Y = (const float*)d_in[1];
    float* out = (float*)d_out;

    norms_kernel<<<2 * N, 256>>>(X, Y);
    cost_gemm<<<dim3(N / GBN, N / GBM), 256>>>(X, Y);
    init_g<<<N / 256, 256>>>();

    for (int it = 0; it < 50; it++) {
        fused_pass<<<FBLOCKS, 512>>>();
        combine1<<<dim3(N / 256, P2), 256>>>();
        combine2<<<N / 256, 256>>>();
    }

    final_fg<<<N / 256, 256>>>();
    pi_cost<<<N, 256>>>(out);
    cost_reduce<<<1, 1024>>>(out);
}